// round 15
// baseline (speedup 1.0000x reference)
#include <cuda_runtime.h>
#include <cuda_bf16.h>
#include <cstdint>

#define BATCH 8
#define CH    256
#define HW    16384   // 128*128
#define TOK   128
#define HEADS 8
#define DH    64
#define INNER 512
#define NTA   512     // attn threads (16 warps)

// ---- scratch (device globals; no runtime allocation) ----
// bf16 split operands
__device__ __nv_bfloat16 g_w_hi[(size_t)3*INNER*CH];
__device__ __nv_bfloat16 g_w_lo[(size_t)3*INNER*CH];
__device__ __nv_bfloat16 g_wo_hi[(size_t)CH*INNER];   // 0.5*wout split
__device__ __nv_bfloat16 g_wo_lo[(size_t)CH*INNER];
__device__ __nv_bfloat16 g_xt_hi[(size_t)BATCH*HW*CH];  // [b][hw][c]
__device__ __nv_bfloat16 g_xt_lo[(size_t)BATCH*HW*CH];
// q/k/v bf16 hi/lo: [b][o=head*64+d][hw]
__device__ __nv_bfloat16 g_q_hi[(size_t)BATCH*INNER*HW];
__device__ __nv_bfloat16 g_q_lo[(size_t)BATCH*INNER*HW];
__device__ __nv_bfloat16 g_k_hi[(size_t)BATCH*INNER*HW];
__device__ __nv_bfloat16 g_k_lo[(size_t)BATCH*INNER*HW];
__device__ __nv_bfloat16 g_v_hi[(size_t)BATCH*INNER*HW];
__device__ __nv_bfloat16 g_v_lo[(size_t)BATCH*INNER*HW];
// attn outputs bf16 hi/lo: [b][o][hw]
__device__ __nv_bfloat16 g_oh_hi[(size_t)BATCH*INNER*HW];
__device__ __nv_bfloat16 g_oh_lo[(size_t)BATCH*INNER*HW];
__device__ __nv_bfloat16 g_ow_hi[(size_t)BATCH*INNER*HW];
__device__ __nv_bfloat16 g_ow_lo[(size_t)BATCH*INNER*HW];

// ============================================================
// helpers
// ============================================================
__device__ __forceinline__ uint32_t smem_u32(const void* p) {
    uint32_t a;
    asm("{ .reg .u64 t; cvta.to.shared.u64 t, %1; cvt.u32.u64 %0, t; }" : "=r"(a) : "l"(p));
    return a;
}
__device__ __forceinline__ void ldsm4(uint32_t a, uint32_t& r0, uint32_t& r1, uint32_t& r2, uint32_t& r3) {
    asm volatile("ldmatrix.sync.aligned.m8n8.x4.shared.b16 {%0,%1,%2,%3}, [%4];"
                 : "=r"(r0),"=r"(r1),"=r"(r2),"=r"(r3) : "r"(a));
}
__device__ __forceinline__ void ldsm4t(uint32_t a, uint32_t& r0, uint32_t& r1, uint32_t& r2, uint32_t& r3) {
    asm volatile("ldmatrix.sync.aligned.m8n8.x4.trans.shared.b16 {%0,%1,%2,%3}, [%4];"
                 : "=r"(r0),"=r"(r1),"=r"(r2),"=r"(r3) : "r"(a));
}
__device__ __forceinline__ void mma16816(float* d, const uint32_t* a, const uint32_t* b) {
    asm volatile("mma.sync.aligned.m16n8k16.row.col.f32.bf16.bf16.f32 "
                 "{%0,%1,%2,%3}, {%4,%5,%6,%7}, {%8,%9}, {%0,%1,%2,%3};"
                 : "+f"(d[0]),"+f"(d[1]),"+f"(d[2]),"+f"(d[3])
                 : "r"(a[0]),"r"(a[1]),"r"(a[2]),"r"(a[3]), "r"(b[0]),"r"(b[1]));
}
__device__ __forceinline__ void bf16_split(float v, __nv_bfloat16& h, __nv_bfloat16& l) {
    h = __float2bfloat16(v);
    l = __float2bfloat16(v - __bfloat162float(h));
}
__device__ __forceinline__ void cp16(uint32_t dst, const void* src) {
    asm volatile("cp.async.cg.shared.global [%0], [%1], 16;" :: "r"(dst), "l"(src));
}
__device__ __forceinline__ void cp_commit() { asm volatile("cp.async.commit_group;" ::: "memory"); }
template<int N> __device__ __forceinline__ void cp_wait() {
    asm volatile("cp.async.wait_group %0;" :: "n"(N) : "memory");
}

// 3-pass split mma, warp tile 32x32 (2 m16 x 4 n8)
__device__ __forceinline__ void mma_triple2(
    float (&acc)[2][4][4],
    const uint32_t (&ah)[2][4], const uint32_t (&al)[2][4],
    const uint32_t (&bh)[4][2], const uint32_t (&bl)[4][2])
{
    #pragma unroll
    for (int mt = 0; mt < 2; mt++)
        #pragma unroll
        for (int nt = 0; nt < 4; nt++) {
            mma16816(acc[mt][nt], ah[mt], bh[nt]);
            mma16816(acc[mt][nt], ah[mt], bl[nt]);
            mma16816(acc[mt][nt], al[mt], bh[nt]);
        }
}

// ============================================================
// K0a: split w_qkv and 0.5*w_out into bf16 hi/lo
// ============================================================
#define NWQKV (3*INNER*CH)   // 393216
#define NWOUT (CH*INNER)     // 131072
__global__ void __launch_bounds__(256) convert_w_kernel(
    const float* __restrict__ wqkv, const float* __restrict__ wout)
{
    int i = blockIdx.x * 256 + threadIdx.x;
    if (i < NWQKV) {
        __nv_bfloat16 h, l;
        bf16_split(wqkv[i], h, l);
        g_w_hi[i] = h; g_w_lo[i] = l;
    } else {
        int j = i - NWQKV;
        __nv_bfloat16 h, l;
        bf16_split(0.5f * wout[j], h, l);
        g_wo_hi[j] = h; g_wo_lo[j] = l;
    }
}

// ============================================================
// K0b: transpose x [b][c][hw] -> xt [b][hw][c], split bf16 hi/lo
// ============================================================
__global__ void __launch_bounds__(256) transpose_x_kernel(const float* __restrict__ x) {
    __shared__ float ts[32][33];
    const int b = blockIdx.z, c0 = blockIdx.y * 32, hw0 = blockIdx.x * 32;
    const int tx = threadIdx.x & 31, ty = threadIdx.x >> 5;
    const float* xb = x + ((size_t)b * CH + c0) * HW + hw0;
    #pragma unroll
    for (int i = 0; i < 4; i++) {
        int c = ty + i * 8;
        ts[c][tx] = xb[(size_t)c * HW + tx];
    }
    __syncthreads();
    size_t ob = ((size_t)b * HW + hw0) * CH + c0;
    #pragma unroll
    for (int i = 0; i < 4; i++) {
        int r = ty + i * 8;
        __nv_bfloat16 h, l;
        bf16_split(ts[tx][r], h, l);
        g_xt_hi[ob + (size_t)r * CH + tx] = h;
        g_xt_lo[ob + (size_t)r * CH + tx] = l;
    }
}

// ============================================================
// K1: qkv = w_qkv @ x via mma.sync bf16 3-pass split, 256 threads.
// CTA tile 128m x 256n, warp grid 2m x 4n, warp tile 64x64.
// 2-stage cp.async ring. grid (12 m, 64 n, 8 b).
// ============================================================
#define K1P 72
#define K1_STAGE 110592
#define K1_SMEM  (2 * K1_STAGE)   // 221184

extern __shared__ char k1_sm[];

__device__ __forceinline__ void k1_issue(int m0, int n0, int b, int k0, uint32_t tb, int tid) {
    {
        const __nv_bfloat16* srcs[2] = {
            g_w_hi + (size_t)m0 * CH + k0,
            g_w_lo + (size_t)m0 * CH + k0 };
        #pragma unroll
        for (int t = 0; t < 2; t++) {
            uint32_t dstb = tb + t * 18432;
            const __nv_bfloat16* src = srcs[t];
            #pragma unroll
            for (int it = 0; it < 4; it++) {
                int idx = tid + it * 256;
                int r = idx >> 3, c = idx & 7;
                cp16(dstb + r * 144 + c * 16, src + (size_t)r * CH + c * 8);
            }
        }
    }
    {
        const __nv_bfloat16* srcs[2] = {
            g_xt_hi + ((size_t)b * HW + n0) * CH + k0,
            g_xt_lo + ((size_t)b * HW + n0) * CH + k0 };
        #pragma unroll
        for (int t = 0; t < 2; t++) {
            uint32_t dstb = tb + 36864 + t * 36864;
            const __nv_bfloat16* src = srcs[t];
            #pragma unroll
            for (int it = 0; it < 8; it++) {
                int idx = tid + it * 256;
                int r = idx >> 3, c = idx & 7;
                cp16(dstb + r * 144 + c * 16, src + (size_t)r * CH + c * 8);
            }
        }
    }
    cp_commit();
}

__global__ void __launch_bounds__(256) qkv_mma_kernel() {
    const int tid = threadIdx.x;
    const int lane = tid & 31, warp = tid >> 5;
    const int wm = warp >> 2, wn = warp & 3;
    const int m0 = blockIdx.x * 128;
    const int n0 = blockIdx.y * 256;
    const int b  = blockIdx.z;
    const uint32_t sbase = smem_u32(k1_sm);

    float acc[4][8][4];
    #pragma unroll
    for (int i = 0; i < 4; i++)
        #pragma unroll
        for (int j = 0; j < 8; j++)
            #pragma unroll
            for (int q = 0; q < 4; q++) acc[i][j][q] = 0.f;

    k1_issue(m0, n0, b, 0, sbase, tid);

    for (int s = 0; s < 4; s++) {
        if (s > 0) __syncthreads();
        if (s < 3)
            k1_issue(m0, n0, b, (s + 1) * 64, sbase + ((s + 1) & 1) * K1_STAGE, tid);
        if (s < 3) { cp_wait<1>(); } else { cp_wait<0>(); }
        __syncthreads();

        const char* tb = k1_sm + (s & 1) * K1_STAGE;
        const __nv_bfloat16* Ah = reinterpret_cast<const __nv_bfloat16*>(tb);
        const __nv_bfloat16* Al = reinterpret_cast<const __nv_bfloat16*>(tb + 18432);
        const __nv_bfloat16* Bh = reinterpret_cast<const __nv_bfloat16*>(tb + 36864);
        const __nv_bfloat16* Bl = reinterpret_cast<const __nv_bfloat16*>(tb + 73728);

        #pragma unroll
        for (int ks = 0; ks < 4; ks++) {
            const int kk = ks * 16;
            uint32_t ah[4][4], al[4][4];
            #pragma unroll
            for (int mt = 0; mt < 4; mt++) {
                uint32_t off = (wm * 64 + mt * 16 + (lane & 15)) * K1P + kk + (lane >> 4) * 8;
                ldsm4(smem_u32(Ah + off), ah[mt][0], ah[mt][1], ah[mt][2], ah[mt][3]);
                ldsm4(smem_u32(Al + off), al[mt][0], al[mt][1], al[mt][2], al[mt][3]);
            }
            #pragma unroll
            for (int nh = 0; nh < 2; nh++) {
                uint32_t bh[4][2], bl[4][2];
                #pragma unroll
                for (int np = 0; np < 2; np++) {
                    int nrow = wn * 64 + nh * 32 + np * 16 + (lane & 7) + ((lane >> 4) & 1) * 8;
                    int kcol = kk + ((lane >> 3) & 1) * 8;
                    uint32_t off = nrow * K1P + kcol;
                    ldsm4(smem_u32(Bh + off), bh[np*2][0], bh[np*2][1], bh[np*2+1][0], bh[np*2+1][1]);
                    ldsm4(smem_u32(Bl + off), bl[np*2][0], bl[np*2][1], bl[np*2+1][0], bl[np*2+1][1]);
                }
                #pragma unroll
                for (int mt = 0; mt < 4; mt++)
                    #pragma unroll
                    for (int nt = 0; nt < 4; nt++) {
                        mma16816(acc[mt][nh*4+nt], ah[mt], bh[nt]);
                        mma16816(acc[mt][nh*4+nt], ah[mt], bl[nt]);
                        mma16816(acc[mt][nh*4+nt], al[mt], bh[nt]);
                    }
            }
        }
    }

    // epilogue -> q/k/v bf16 hi/lo
    const int g = lane >> 2, tig = lane & 3;
    #pragma unroll
    for (int mt = 0; mt < 4; mt++) {
        int mbase = m0 + wm * 64 + mt * 16;
        #pragma unroll
        for (int half = 0; half < 2; half++) {
            int m = mbase + g + half * 8;
            int kind = m >> 9, oo = m & 511;
            __nv_bfloat16 *dh, *dl;
            if (kind == 0)      { dh = g_q_hi; dl = g_q_lo; }
            else if (kind == 1) { dh = g_k_hi; dl = g_k_lo; }
            else                { dh = g_v_hi; dl = g_v_lo; }
            size_t rbase = ((size_t)b * INNER + oo) * HW + n0;
            #pragma unroll
            for (int nt = 0; nt < 8; nt++) {
                int col = wn * 64 + nt * 8 + tig * 2;
                __nv_bfloat16 h0, l0, h1, l1;
                bf16_split(acc[mt][nt][half*2],   h0, l0);
                bf16_split(acc[mt][nt][half*2+1], h1, l1);
                *reinterpret_cast<__nv_bfloat162*>(dh + rbase + col) = __nv_bfloat162(h0, h1);
                *reinterpret_cast<__nv_bfloat162*>(dl + rbase + col) = __nv_bfloat162(l0, l1);
            }
        }
    }
}

// ============================================================
// K2: axial attention via mma.sync bf16 3-pass split, 512 threads.
// epilogue writes O as bf16 hi/lo (K3 operands).
// ============================================================
#define PS 136
#define QP 72

#define AT_TBUF 73728
#define AT_PH   139264
#define AT_PL   174080
#define AT_SMEM (3 * AT_TBUF)   // 221184

extern __shared__ char at_sm[];

__device__ __forceinline__ void attn_issue_qk(
    const __nv_bfloat16* s0, const __nv_bfloat16* s1,
    const __nv_bfloat16* s2, const __nv_bfloat16* s3,
    int s, uint32_t tb, int tid, int mode)
{
    const __nv_bfloat16* srcs[4] = { s0, s1, s2, s3 };
    const int d = s >> 1, off = (s & 1) * 64;
    if (mode == 0) {
        #pragma unroll
        for (int t = 0; t < 4; t++) {
            const __nv_bfloat16* src = srcs[t] + (size_t)d * HW + off;
            uint32_t dstb = tb + t * 18432;
            #pragma unroll
            for (int it = 0; it < 2; it++) {
                int idx = tid + it * NTA;
                int r = idx >> 3, c = idx & 7;
                cp16(dstb + r * 144 + c * 16, src + r * TOK + c * 8);
            }
        }
    } else {
        #pragma unroll
        for (int t = 0; t < 4; t++) {
            const __nv_bfloat16* src = srcs[t] + (size_t)d * HW + (size_t)off * TOK;
            uint32_t dstb = tb + t * 17408;
            #pragma unroll
            for (int it = 0; it < 2; it++) {
                int idx = tid + it * NTA;
                int r = idx >> 4, c = idx & 15;
                cp16(dstb + r * 272 + c * 16, src + r * TOK + c * 8);
            }
        }
    }
    cp_commit();
}

__device__ __forceinline__ void attn_issue_v(
    const __nv_bfloat16* vh, const __nv_bfloat16* vl, int d, uint32_t vb, int tid)
{
    #pragma unroll
    for (int sp = 0; sp < 2; sp++) {
        const __nv_bfloat16* src = (sp ? vl : vh) + (size_t)d * HW;
        uint32_t dstb = vb + sp * 34816;
        #pragma unroll
        for (int it = 0; it < 4; it++) {
            int idx = tid + it * NTA;
            int r = idx >> 4, c = idx & 15;
            cp16(dstb + r * 272 + c * 16, src + r * TOK + c * 8);
        }
    }
    cp_commit();
}

__global__ void __launch_bounds__(NTA) attn_mma_kernel()
{
    float* Ssm = reinterpret_cast<float*>(at_sm);
    __nv_bfloat16* Ph = reinterpret_cast<__nv_bfloat16*>(at_sm + AT_PH);
    __nv_bfloat16* Pl = reinterpret_cast<__nv_bfloat16*>(at_sm + AT_PL);

    const int tid = threadIdx.x;
    const int lane = tid & 31, warp = tid >> 5;
    const int wm = warp >> 2, wn = warp & 3;
    const int g = lane >> 2, tig = lane & 3;
    const int bh2 = blockIdx.x, mode = blockIdx.y;
    const int b = bh2 >> 3, head = bh2 & 7;
    const uint32_t sbase = smem_u32(at_sm);

    const size_t pbase = ((size_t)b * INNER + head * DH) * HW;
    const __nv_bfloat16* __restrict__ qh = g_q_hi + pbase;
    const __nv_bfloat16* __restrict__ ql = g_q_lo + pbase;
    const __nv_bfloat16* __restrict__ kh = g_k_hi + pbase;
    const __nv_bfloat16* __restrict__ kl = g_k_lo + pbase;
    const __nv_bfloat16* __restrict__ vh = g_v_hi + pbase;
    const __nv_bfloat16* __restrict__ vl = g_v_lo + pbase;

    // ================= phase 1: S = Q K^T =================
    {
        float acc[2][4][4];
        #pragma unroll
        for (int i = 0; i < 2; i++)
            #pragma unroll
            for (int j = 0; j < 4; j++)
                #pragma unroll
                for (int q = 0; q < 4; q++) acc[i][j][q] = 0.f;

        attn_issue_qk(qh, ql, kh, kl, 0, sbase,           tid, mode);
        attn_issue_qk(qh, ql, kh, kl, 1, sbase + AT_TBUF, tid, mode);

        for (int s = 0; s < 128; s++) {
            if (s < 127) { cp_wait<1>(); } else { cp_wait<0>(); }
            __syncthreads();

            const char* tbase = at_sm + (s % 3) * AT_TBUF;

            if (mode == 0) {
                const __nv_bfloat16* Qh = reinterpret_cast<const __nv_bfloat16*>(tbase);
                const __nv_bfloat16* Ql = reinterpret_cast<const __nv_bfloat16*>(tbase + 18432);
                const __nv_bfloat16* Kh = reinterpret_cast<const __nv_bfloat16*>(tbase + 36864);
                const __nv_bfloat16* Kl = reinterpret_cast<const __nv_bfloat16*>(tbase + 55296);
                #pragma unroll
                for (int ks = 0; ks < 4; ks++) {
                    const int kk = ks * 16;
                    uint32_t ah[2][4], al[2][4], bh[4][2], bl[4][2];
                    #pragma unroll
                    for (int mt = 0; mt < 2; mt++) {
                        uint32_t off = (wm*32 + mt*16 + (lane & 15)) * QP + kk + (lane >> 4) * 8;
                        ldsm4(smem_u32(Qh + off), ah[mt][0], ah[mt][1], ah[mt][2], ah[mt][3]);
                        ldsm4(smem_u32(Ql + off), al[mt][0], al[mt][1], al[mt][2], al[mt][3]);
                    }
                    #pragma unroll
                    for (int np = 0; np < 2; np++) {
                        int nrow = wn*32 + np*16 + (lane & 7) + ((lane >> 4) & 1) * 8;
                        int kcol = kk + ((lane >> 3) & 1) * 8;
                        uint32_t off = nrow * QP + kcol;
                        ldsm4(smem_u32(Kh + off), bh[np*2][0], bh[np*2][1], bh[np*2+1][0], bh[np*2+1][1]);
                        ldsm4(smem_u32(Kl + off), bl[np*2][0], bl[np*2][1], bl[np*2+1][0], bl[np*2+1][1]);
                    }
                    mma_triple2(acc, ah, al, bh, bl);
                }
            } else {
                const __nv_bfloat16* Qh = reinterpret_cast<const __nv_bfloat16*>(tbase);
                const __nv_bfloat16* Ql = reinterpret_cast<const __nv_bfloat16*>(tbase + 17408);
                const __nv_bfloat16* Kh = reinterpret_cast<const __nv_bfloat16*>(tbase + 34816);
                const __nv_bfloat16* Kl = reinterpret_cast<const __nv_bfloat16*>(tbase + 52224);
                #pragma unroll
                for (int ks = 0; ks < 4; ks++) {
                    const int kk = ks * 16;
                    uint32_t ah[2][4], al[2][4], bh[4][2], bl[4][2];
                    #pragma unroll
                    for (int mt = 0; mt < 2; mt++) {
                        uint32_t off = (kk + (lane & 7) + ((lane >> 4) & 1) * 8) * PS
                                       + wm*32 + mt*16 + ((lane >> 3) & 1) * 8;
                        ldsm4t(smem_u32(Qh + off), ah[mt][0], ah[mt][1], ah[mt][2], ah[mt][3]);
                        ldsm4t(smem_u32(Ql + off), al[mt][0], al[mt][1], al[mt][2], al[mt][3]);
                    }
                    #pragma unroll
                    for (int np = 0; np < 2; np++) {
                        int krow = kk + (lane & 7) + ((lane >> 3) & 1) * 8;
                        int ncol = wn*32 + np*16 + ((lane >> 4) & 1) * 8;
                        uint32_t off = krow * PS + ncol;
                        ldsm4t(smem_u32(Kh + off), bh[np*2][0], bh[np*2][1], bh[np*2+1][0], bh[np*2+1][1]);
                        ldsm4t(smem_u32(Kl + off), bl[np*2][0], bl[np*2][1], bl[np*2+1][0], bl[np*2+1][1]);
                    }
                    mma_triple2(acc, ah, al, bh, bl);
                }
            }

            if (s + 2 <= 127)
                attn_issue_qk(qh, ql, kh, kl, s + 2, sbase + ((s + 2) % 3) * AT_TBUF, tid, mode);
        }

        #pragma unroll
        for (int mt = 0; mt < 2; mt++) {
            int i0 = wm*32 + mt*16 + g;
            #pragma unroll
            for (int nt = 0; nt < 4; nt++) {
                int j0 = wn*32 + nt*8 + tig*2;
                Ssm[j0 * TOK + i0]           = acc[mt][nt][0];
                Ssm[(j0+1) * TOK + i0]       = acc[mt][nt][1];
                Ssm[j0 * TOK + i0 + 8]       = acc[mt][nt][2];
                Ssm[(j0+1) * TOK + i0 + 8]   = acc[mt][nt][3];
            }
        }
    }
    __syncthreads();

    // ================= softmax over j, write P hi/lo =================
    if (tid < TOK) {
        const int i = tid;
        float mx = -1e30f;
        for (int j = 0; j < TOK; j++) mx = fmaxf(mx, Ssm[j * TOK + i]);
        float s = 0.f;
        for (int j = 0; j < TOK; j++) {
            float e = __expf((Ssm[j * TOK + i] - mx) * 0.125f);
            s += e;
            Ssm[j * TOK + i] = e;
        }
        float inv = 1.f / s;
        for (int j = 0; j < TOK; j++) {
            float pv = Ssm[j * TOK + i] * inv;
            __nv_bfloat16 h, l;
            bf16_split(pv, h, l);
            Ph[j * PS + i] = h;
            Pl[j * PS + i] = l;
        }
    }
    __syncthreads();

    // ================= phase 2: O = P V =================
    __nv_bfloat16* doh = ((mode == 0) ? g_oh_hi : g_ow_hi) + pbase;
    __nv_bfloat16* dol = ((mode == 0) ? g_oh_lo : g_ow_lo) + pbase;

    attn_issue_v(vh, vl, 0, sbase, tid);

    for (int d = 0; d < DH; d++) {
        const int buf = d & 1;
        if (d < DH - 1) {
            attn_issue_v(vh, vl, d + 1, sbase + (buf ^ 1) * 69632, tid);
            cp_wait<1>();
        } else {
            cp_wait<0>();
        }
        __syncthreads();

        const __nv_bfloat16* Vh = reinterpret_cast<const __nv_bfloat16*>(at_sm + buf * 69632);
        const __nv_bfloat16* Vl = Vh + 128 * PS;

        float oacc[2][4][4];
        #pragma unroll
        for (int i = 0; i < 2; i++)
            #pragma unroll
            for (int j = 0; j < 4; j++)
                #pragma unroll
                for (int q = 0; q < 4; q++) oacc[i][j][q] = 0.f;

        if (mode == 0) {
            #pragma unroll
            for (int ks = 0; ks < 8; ks++) {
                const int kk = ks * 16;
                uint32_t ah[2][4], al[2][4], bh[4][2], bl[4][2];
                #pragma unroll
                for (int mt = 0; mt < 2; mt++) {
                    uint32_t off = (kk + (lane & 7) + ((lane >> 4) & 1) * 8) * PS
                                   + wm*32 + mt*16 + ((lane >> 3) & 1) * 8;
                    ldsm4t(smem_u32(Ph + off), ah[mt][0], ah[mt][1], ah[mt][2], ah[mt][3]);
                    ldsm4t(smem_u32(Pl + off), al[mt][0], al[mt][1], al[mt][2], al[mt][3]);
                }
                #pragma unroll
                for (int np = 0; np < 2; np++) {
                    int krow = kk + (lane & 7) + ((lane >> 3) & 1) * 8;
                    int ncol = wn*32 + np*16 + ((lane >> 4) & 1) * 8;
                    uint32_t off = krow * PS + ncol;
                    ldsm4t(smem_u32(Vh + off), bh[np*2][0], bh[np*2][1], bh[np*2+1][0], bh[np*2+1][1]);
                    ldsm4t(smem_u32(Vl + off), bl[np*2][0], bl[np*2][1], bl[np*2+1][0], bl[np*2+1][1]);
                }
                mma_triple2(oacc, ah, al, bh, bl);
            }
        } else {
            #pragma unroll
            for (int ks = 0; ks < 8; ks++) {
                const int kk = ks * 16;
                uint32_t ah[2][4], al[2][4], bh[4][2], bl[4][2];
                #pragma unroll
                for (int mt = 0; mt < 2; mt++) {
                    uint32_t off = (wm*32 + mt*16 + (lane & 15)) * PS + kk + (lane >> 4) * 8;
                    ldsm4(smem_u32(Vh + off), ah[mt][0], ah[mt][1], ah[mt][2], ah[mt][3]);
                    ldsm4(smem_u32(Vl + off), al[mt][0], al[mt][1], al[mt][2], al[mt][3]);
                }
                #pragma unroll
                for (int np = 0; np < 2; np++) {
                    int krow = kk + (lane & 7) + ((lane >> 3) & 1) * 8;
                    int ncol = wn*32 + np*16 + ((lane >> 4) & 1) * 8;
                    uint32_t off = krow * PS + ncol;
                    ldsm4t(smem_u32(Ph + off), bh[np*2][0], bh[np*2][1], bh[np*2+1][0], bh[np*2+1][1]);
                    ldsm4t(smem_u32(Pl + off), bl[np*2][0], bl[np*2][1], bl[np*2+1][0], bl[np*2+1][1]);
                }
                mma_triple2(oacc, ah, al, bh, bl);
            }
        }

        // epilogue: write O plane as bf16 hi/lo (coalesced)
        size_t dplane = (size_t)d * HW;
        #pragma unroll
        for (int mt = 0; mt < 2; mt++) {
            #pragma unroll
            for (int half = 0; half < 2; half++) {
                int m = wm*32 + mt*16 + g + half*8;
                size_t rowb = dplane + (size_t)m * TOK;
                #pragma unroll
                for (int nt = 0; nt < 4; nt++) {
                    int col = wn*32 + nt*8 + tig*2;
                    __nv_bfloat16 h0, l0, h1, l1;
                    bf16_split(oacc[mt][nt][half*2],   h0, l0);
                    bf16_split(oacc[mt][nt][half*2+1], h1, l1);
                    *reinterpret_cast<__nv_bfloat162*>(doh + rowb + col) = __nv_bfloat162(h0, h1);
                    *reinterpret_cast<__nv_bfloat162*>(dol + rowb + col) = __nv_bfloat162(l0, l1);
                }
            }
        }
        __syncthreads();
    }
}

// ============================================================
// K3: out = (0.5 wout)@H + (0.5 wout)@W + b_out + x.
// K1-style pipeline: CTA 128m x 256n, warp tile 64x64, K=1024 in 16 slabs.
// B is [k][n]-major (attn output layout) -> trans-B ldsm.
// stage: A_hi [128][72] @0, A_lo @18432, B_hi [64][264] @36864,
//        B_lo @70656. stage = 104448, 2 stages = 208896.
// ============================================================
#define K3P  72
#define K3BN 264
#define K3_STAGE 104448
#define K3_SMEM  (2 * K3_STAGE)   // 208896

extern __shared__ char k3_sm[];

__device__ __forceinline__ void k3_issue(int m0, int n0, int b, int s, uint32_t tb, int tid) {
    const int kind = s >> 3, k0 = (s & 7) * 64;
    {
        const __nv_bfloat16* srcs[2] = {
            g_wo_hi + (size_t)m0 * INNER + k0,
            g_wo_lo + (size_t)m0 * INNER + k0 };
        #pragma unroll
        for (int t = 0; t < 2; t++) {
            uint32_t dstb = tb + t * 18432;
            const __nv_bfloat16* src = srcs[t];
            #pragma unroll
            for (int it = 0; it < 4; it++) {
                int idx = tid + it * 256;
                int r = idx >> 3, c = idx & 7;
                cp16(dstb + r * 144 + c * 16, src + (size_t)r * INNER + c * 8);
            }
        }
    }
    {
        const __nv_bfloat16* bh = (kind ? g_ow_hi : g_oh_hi) + ((size_t)b * INNER + k0) * HW + n0;
        const __nv_bfloat16* bl = (kind ? g_ow_lo : g_oh_lo) + ((size_t)b * INNER + k0) * HW + n0;
        const __nv_bfloat16* srcs[2] = { bh, bl };
        #pragma unroll
        for (int t = 0; t < 2; t++) {
            uint32_t dstb = tb + 36864 + t * 33792;
            const __nv_bfloat16* src = srcs[t];
            #pragma unroll
            for (int it = 0; it < 8; it++) {   // 64 rows x 32 chunks = 2048
                int idx = tid + it * 256;
                int r = idx >> 5, c = idx & 31;
                cp16(dstb + r * 528 + c * 16, src + (size_t)r * HW + c * 8);
            }
        }
    }
    cp_commit();
}

__global__ void __launch_bounds__(256) out_mma_kernel(
    const float* __restrict__ x, const float* __restrict__ bout, float* __restrict__ out)
{
    const int tid = threadIdx.x;
    const int lane = tid & 31, warp = tid >> 5;
    const int wm = warp >> 2, wn = warp & 3;
    const int m0 = blockIdx.x * 128;
    const int n0 = blockIdx.y * 256;
    const int b  = blockIdx.z;
    const uint32_t sbase = smem_u32(k3_sm);

    float acc[4][8][4];
    #pragma unroll
    for (int i = 0; i < 4; i++)
        #pragma unroll
        for (int j = 0; j < 8; j++)
            #pragma unroll
            for (int q = 0; q < 4; q++) acc[i][j][q] = 0.f;

    k3_issue(m0, n0, b, 0, sbase, tid);

    for (int s = 0; s < 16; s++) {
        if (s > 0) __syncthreads();
        if (s < 15)
            k3_issue(m0, n0, b, s + 1, sbase + ((s + 1) & 1) * K3_STAGE, tid);
        if (s < 15) { cp_wait<1>(); } else { cp_wait<0>(); }
        __syncthreads();

        const char* tb = k3_sm + (s & 1) * K3_STAGE;
        const __nv_bfloat16* Ah = reinterpret_cast<const __nv_bfloat16*>(tb);
        const __nv_bfloat16* Al = reinterpret_cast<const __nv_bfloat16*>(tb + 18432);
        const __nv_bfloat16* Bh = reinterpret_cast<const __nv_bfloat16*>(tb + 36864);
        const __nv_bfloat16* Bl = reinterpret_cast<const __nv_bfloat16*>(tb + 70656);

        #pragma unroll
        for (int ks = 0; ks < 4; ks++) {
            const int kk = ks * 16;
            uint32_t ah[4][4], al[4][4];
            #pragma unroll
            for (int mt = 0; mt < 4; mt++) {
                uint32_t off = (wm * 64 + mt * 16 + (lane & 15)) * K3P + kk + (lane >> 4) * 8;
                ldsm4(smem_u32(Ah + off), ah[mt][0], ah[mt][1], ah[mt][2], ah[mt][3]);
                ldsm4(smem_u32(Al + off), al[mt][0], al[mt][1], al[mt][2], al[mt][3]);
            }
            #pragma unroll
            for (int nh = 0; nh < 2; nh++) {
                uint32_t bh[4][2], bl[4][2];
                #pragma unroll
                for (int np = 0; np < 2; np++) {
                    int krow = kk + (lane & 7) + ((lane >> 3) & 1) * 8;
                    int ncol = wn * 64 + nh * 32 + np * 16 + ((lane >> 4) & 1) * 8;
                    uint32_t off = krow * K3BN + ncol;
                    ldsm4t(smem_u32(Bh + off), bh[np*2][0], bh[np*2][1], bh[np*2+1][0], bh[np*2+1][1]);
                    ldsm4t(smem_u32(Bl + off), bl[np*2][0], bl[np*2][1], bl[np*2+1][0], bl[np*2+1][1]);
                }
                #pragma unroll
                for (int mt = 0; mt < 4; mt++)
                    #pragma unroll
                    for (int nt = 0; nt < 4; nt++) {
                        mma16816(acc[mt][nh*4+nt], ah[mt], bh[nt]);
                        mma16816(acc[mt][nh*4+nt], ah[mt], bl[nt]);
                        mma16816(acc[mt][nh*4+nt], al[mt], bh[nt]);
                    }
            }
        }
    }

    // epilogue: + bias + residual
    const int g = lane >> 2, tig = lane & 3;
    #pragma unroll
    for (int mt = 0; mt < 4; mt++) {
        int mbase = m0 + wm * 64 + mt * 16;
        #pragma unroll
        for (int half = 0; half < 2; half++) {
            int m = mbase + g + half * 8;
            float bias = bout[m];
            size_t rbase = ((size_t)b * CH + m) * HW + n0;
            #pragma unroll
            for (int nt = 0; nt < 8; nt++) {
                int col = wn * 64 + nt * 8 + tig * 2;
                float2 xv = *reinterpret_cast<const float2*>(x + rbase + col);
                *reinterpret_cast<float2*>(out + rbase + col) =
                    make_float2(acc[mt][nt][half*2]   + bias + xv.x,
                                acc[mt][nt][half*2+1] + bias + xv.y);
            }
        }
    }
}

// ============================================================
extern "C" void kernel_launch(void* const* d_in, const int* in_sizes, int n_in,
                              void* d_out, int out_size) {
    (void)in_sizes; (void)n_in; (void)out_size;
    const float* x    = (const float*)d_in[0];
    const float* wqkv = (const float*)d_in[1];
    const float* wout = (const float*)d_in[2];
    const float* bout = (const float*)d_in[3];
    float* out = (float*)d_out;

    cudaFuncSetAttribute(qkv_mma_kernel,  cudaFuncAttributeMaxDynamicSharedMemorySize, K1_SMEM);
    cudaFuncSetAttribute(attn_mma_kernel, cudaFuncAttributeMaxDynamicSharedMemorySize, AT_SMEM);
    cudaFuncSetAttribute(out_mma_kernel,  cudaFuncAttributeMaxDynamicSharedMemorySize, K3_SMEM);

    convert_w_kernel<<<(NWQKV + NWOUT) / 256, 256>>>(wqkv, wout);
    transpose_x_kernel<<<dim3(HW / 32, CH / 32, BATCH), 256>>>(x);
    qkv_mma_kernel<<<dim3(1536 / 128, HW / 256, BATCH), 256, K1_SMEM>>>();
    attn_mma_kernel<<<dim3(BATCH * HEADS, 2), NTA, AT_SMEM>>>();
    out_mma_kernel<<<dim3(CH / 128, HW / 256, BATCH), 256, K3_SMEM>>>(x, bout, out);
}

// round 16
// speedup vs baseline: 1.1161x; 1.1161x over previous
#include <cuda_runtime.h>
#include <cuda_bf16.h>
#include <cstdint>

#define BATCH 8
#define CH    256
#define HW    16384   // 128*128
#define TOK   128
#define HEADS 8
#define DH    64
#define INNER 512
#define NTA   512     // attn threads (16 warps)

// ---- scratch (device globals; no runtime allocation) ----
__device__ float g_bufH[(size_t)BATCH*INNER*HW];   // row-attn output  [b][o][hw]
__device__ float g_bufW[(size_t)BATCH*INNER*HW];   // col-attn output  [b][o][hw]
// bf16 split operands
__device__ __nv_bfloat16 g_w_hi[(size_t)3*INNER*CH];
__device__ __nv_bfloat16 g_w_lo[(size_t)3*INNER*CH];
__device__ __nv_bfloat16 g_wo_hi[(size_t)CH*INNER];
__device__ __nv_bfloat16 g_wo_lo[(size_t)CH*INNER];
__device__ __nv_bfloat16 g_xt_hi[(size_t)BATCH*HW*CH];  // [b][hw][c]
__device__ __nv_bfloat16 g_xt_lo[(size_t)BATCH*HW*CH];
// q/k/v bf16 hi/lo: [b][o=head*64+d][hw]
__device__ __nv_bfloat16 g_q_hi[(size_t)BATCH*INNER*HW];
__device__ __nv_bfloat16 g_q_lo[(size_t)BATCH*INNER*HW];
__device__ __nv_bfloat16 g_k_hi[(size_t)BATCH*INNER*HW];
__device__ __nv_bfloat16 g_k_lo[(size_t)BATCH*INNER*HW];
__device__ __nv_bfloat16 g_v_hi[(size_t)BATCH*INNER*HW];
__device__ __nv_bfloat16 g_v_lo[(size_t)BATCH*INNER*HW];
// averaged attn output bf16 hi/lo: [b][k][hw]
__device__ __nv_bfloat16 g_av_hi[(size_t)BATCH*INNER*HW];
__device__ __nv_bfloat16 g_av_lo[(size_t)BATCH*INNER*HW];

// ============================================================
// helpers
// ============================================================
__device__ __forceinline__ uint32_t smem_u32(const void* p) {
    uint32_t a;
    asm("{ .reg .u64 t; cvta.to.shared.u64 t, %1; cvt.u32.u64 %0, t; }" : "=r"(a) : "l"(p));
    return a;
}
__device__ __forceinline__ void ldsm4(uint32_t a, uint32_t& r0, uint32_t& r1, uint32_t& r2, uint32_t& r3) {
    asm volatile("ldmatrix.sync.aligned.m8n8.x4.shared.b16 {%0,%1,%2,%3}, [%4];"
                 : "=r"(r0),"=r"(r1),"=r"(r2),"=r"(r3) : "r"(a));
}
__device__ __forceinline__ void ldsm4t(uint32_t a, uint32_t& r0, uint32_t& r1, uint32_t& r2, uint32_t& r3) {
    asm volatile("ldmatrix.sync.aligned.m8n8.x4.trans.shared.b16 {%0,%1,%2,%3}, [%4];"
                 : "=r"(r0),"=r"(r1),"=r"(r2),"=r"(r3) : "r"(a));
}
__device__ __forceinline__ void mma16816(float* d, const uint32_t* a, const uint32_t* b) {
    asm volatile("mma.sync.aligned.m16n8k16.row.col.f32.bf16.bf16.f32 "
                 "{%0,%1,%2,%3}, {%4,%5,%6,%7}, {%8,%9}, {%0,%1,%2,%3};"
                 : "+f"(d[0]),"+f"(d[1]),"+f"(d[2]),"+f"(d[3])
                 : "r"(a[0]),"r"(a[1]),"r"(a[2]),"r"(a[3]), "r"(b[0]),"r"(b[1]));
}
__device__ __forceinline__ void bf16_split(float v, __nv_bfloat16& h, __nv_bfloat16& l) {
    h = __float2bfloat16(v);
    l = __float2bfloat16(v - __bfloat162float(h));
}
__device__ __forceinline__ void cp16(uint32_t dst, const void* src) {
    asm volatile("cp.async.cg.shared.global [%0], [%1], 16;" :: "r"(dst), "l"(src));
}
__device__ __forceinline__ void cp_commit() { asm volatile("cp.async.commit_group;" ::: "memory"); }
template<int N> __device__ __forceinline__ void cp_wait() {
    asm volatile("cp.async.wait_group %0;" :: "n"(N) : "memory");
}

// 3-pass split mma, warp tile 32x32 (2 m16 x 4 n8)
__device__ __forceinline__ void mma_triple2(
    float (&acc)[2][4][4],
    const uint32_t (&ah)[2][4], const uint32_t (&al)[2][4],
    const uint32_t (&bh)[4][2], const uint32_t (&bl)[4][2])
{
    #pragma unroll
    for (int mt = 0; mt < 2; mt++)
        #pragma unroll
        for (int nt = 0; nt < 4; nt++) {
            mma16816(acc[mt][nt], ah[mt], bh[nt]);
            mma16816(acc[mt][nt], ah[mt], bl[nt]);
            mma16816(acc[mt][nt], al[mt], bh[nt]);
        }
}

// ============================================================
// K0a: split w_qkv and w_out into bf16 hi/lo
// ============================================================
#define NWQKV (3*INNER*CH)   // 393216
#define NWOUT (CH*INNER)     // 131072
__global__ void __launch_bounds__(256) convert_w_kernel(
    const float* __restrict__ wqkv, const float* __restrict__ wout)
{
    int i = blockIdx.x * 256 + threadIdx.x;
    if (i < NWQKV) {
        __nv_bfloat16 h, l;
        bf16_split(wqkv[i], h, l);
        g_w_hi[i] = h; g_w_lo[i] = l;
    } else {
        int j = i - NWQKV;
        __nv_bfloat16 h, l;
        bf16_split(wout[j], h, l);
        g_wo_hi[j] = h; g_wo_lo[j] = l;
    }
}

// ============================================================
// K0b: transpose x [b][c][hw] -> xt [b][hw][c], split bf16 hi/lo
// ============================================================
__global__ void __launch_bounds__(256) transpose_x_kernel(const float* __restrict__ x) {
    __shared__ float ts[32][33];
    const int b = blockIdx.z, c0 = blockIdx.y * 32, hw0 = blockIdx.x * 32;
    const int tx = threadIdx.x & 31, ty = threadIdx.x >> 5;
    const float* xb = x + ((size_t)b * CH + c0) * HW + hw0;
    #pragma unroll
    for (int i = 0; i < 4; i++) {
        int c = ty + i * 8;
        ts[c][tx] = xb[(size_t)c * HW + tx];
    }
    __syncthreads();
    size_t ob = ((size_t)b * HW + hw0) * CH + c0;
    #pragma unroll
    for (int i = 0; i < 4; i++) {
        int r = ty + i * 8;
        __nv_bfloat16 h, l;
        bf16_split(ts[tx][r], h, l);
        g_xt_hi[ob + (size_t)r * CH + tx] = h;
        g_xt_lo[ob + (size_t)r * CH + tx] = l;
    }
}

// ============================================================
// K1: qkv = w_qkv @ x via mma.sync bf16 3-pass split, 256 threads.
// CTA tile 128m x 256n, warp grid 2m x 4n, warp tile 64x64.
// 2-stage cp.async ring. grid (12 m, 64 n, 8 b).
// ============================================================
#define K1P 72
#define K1_STAGE 110592
#define K1_SMEM  (2 * K1_STAGE)   // 221184

extern __shared__ char k1_sm[];

__device__ __forceinline__ void k1_issue(int m0, int n0, int b, int k0, uint32_t tb, int tid) {
    {
        const __nv_bfloat16* srcs[2] = {
            g_w_hi + (size_t)m0 * CH + k0,
            g_w_lo + (size_t)m0 * CH + k0 };
        #pragma unroll
        for (int t = 0; t < 2; t++) {
            uint32_t dstb = tb + t * 18432;
            const __nv_bfloat16* src = srcs[t];
            #pragma unroll
            for (int it = 0; it < 4; it++) {
                int idx = tid + it * 256;
                int r = idx >> 3, c = idx & 7;
                cp16(dstb + r * 144 + c * 16, src + (size_t)r * CH + c * 8);
            }
        }
    }
    {
        const __nv_bfloat16* srcs[2] = {
            g_xt_hi + ((size_t)b * HW + n0) * CH + k0,
            g_xt_lo + ((size_t)b * HW + n0) * CH + k0 };
        #pragma unroll
        for (int t = 0; t < 2; t++) {
            uint32_t dstb = tb + 36864 + t * 36864;
            const __nv_bfloat16* src = srcs[t];
            #pragma unroll
            for (int it = 0; it < 8; it++) {
                int idx = tid + it * 256;
                int r = idx >> 3, c = idx & 7;
                cp16(dstb + r * 144 + c * 16, src + (size_t)r * CH + c * 8);
            }
        }
    }
    cp_commit();
}

__global__ void __launch_bounds__(256) qkv_mma_kernel() {
    const int tid = threadIdx.x;
    const int lane = tid & 31, warp = tid >> 5;
    const int wm = warp >> 2, wn = warp & 3;
    const int m0 = blockIdx.x * 128;
    const int n0 = blockIdx.y * 256;
    const int b  = blockIdx.z;
    const uint32_t sbase = smem_u32(k1_sm);

    float acc[4][8][4];
    #pragma unroll
    for (int i = 0; i < 4; i++)
        #pragma unroll
        for (int j = 0; j < 8; j++)
            #pragma unroll
            for (int q = 0; q < 4; q++) acc[i][j][q] = 0.f;

    k1_issue(m0, n0, b, 0, sbase, tid);

    for (int s = 0; s < 4; s++) {
        if (s > 0) __syncthreads();
        if (s < 3)
            k1_issue(m0, n0, b, (s + 1) * 64, sbase + ((s + 1) & 1) * K1_STAGE, tid);
        if (s < 3) { cp_wait<1>(); } else { cp_wait<0>(); }
        __syncthreads();

        const char* tb = k1_sm + (s & 1) * K1_STAGE;
        const __nv_bfloat16* Ah = reinterpret_cast<const __nv_bfloat16*>(tb);
        const __nv_bfloat16* Al = reinterpret_cast<const __nv_bfloat16*>(tb + 18432);
        const __nv_bfloat16* Bh = reinterpret_cast<const __nv_bfloat16*>(tb + 36864);
        const __nv_bfloat16* Bl = reinterpret_cast<const __nv_bfloat16*>(tb + 73728);

        #pragma unroll
        for (int ks = 0; ks < 4; ks++) {
            const int kk = ks * 16;
            uint32_t ah[4][4], al[4][4];
            #pragma unroll
            for (int mt = 0; mt < 4; mt++) {
                uint32_t off = (wm * 64 + mt * 16 + (lane & 15)) * K1P + kk + (lane >> 4) * 8;
                ldsm4(smem_u32(Ah + off), ah[mt][0], ah[mt][1], ah[mt][2], ah[mt][3]);
                ldsm4(smem_u32(Al + off), al[mt][0], al[mt][1], al[mt][2], al[mt][3]);
            }
            #pragma unroll
            for (int nh = 0; nh < 2; nh++) {
                uint32_t bh[4][2], bl[4][2];
                #pragma unroll
                for (int np = 0; np < 2; np++) {
                    int nrow = wn * 64 + nh * 32 + np * 16 + (lane & 7) + ((lane >> 4) & 1) * 8;
                    int kcol = kk + ((lane >> 3) & 1) * 8;
                    uint32_t off = nrow * K1P + kcol;
                    ldsm4(smem_u32(Bh + off), bh[np*2][0], bh[np*2][1], bh[np*2+1][0], bh[np*2+1][1]);
                    ldsm4(smem_u32(Bl + off), bl[np*2][0], bl[np*2][1], bl[np*2+1][0], bl[np*2+1][1]);
                }
                #pragma unroll
                for (int mt = 0; mt < 4; mt++)
                    #pragma unroll
                    for (int nt = 0; nt < 4; nt++) {
                        mma16816(acc[mt][nh*4+nt], ah[mt], bh[nt]);
                        mma16816(acc[mt][nh*4+nt], ah[mt], bl[nt]);
                        mma16816(acc[mt][nh*4+nt], al[mt], bh[nt]);
                    }
            }
        }
    }

    // epilogue -> q/k/v bf16 hi/lo
    const int g = lane >> 2, tig = lane & 3;
    #pragma unroll
    for (int mt = 0; mt < 4; mt++) {
        int mbase = m0 + wm * 64 + mt * 16;
        #pragma unroll
        for (int half = 0; half < 2; half++) {
            int m = mbase + g + half * 8;
            int kind = m >> 9, oo = m & 511;
            __nv_bfloat16 *dh, *dl;
            if (kind == 0)      { dh = g_q_hi; dl = g_q_lo; }
            else if (kind == 1) { dh = g_k_hi; dl = g_k_lo; }
            else                { dh = g_v_hi; dl = g_v_lo; }
            size_t rbase = ((size_t)b * INNER + oo) * HW + n0;
            #pragma unroll
            for (int nt = 0; nt < 8; nt++) {
                int col = wn * 64 + nt * 8 + tig * 2;
                __nv_bfloat16 h0, l0, h1, l1;
                bf16_split(acc[mt][nt][half*2],   h0, l0);
                bf16_split(acc[mt][nt][half*2+1], h1, l1);
                *reinterpret_cast<__nv_bfloat162*>(dh + rbase + col) = __nv_bfloat162(h0, h1);
                *reinterpret_cast<__nv_bfloat162*>(dl + rbase + col) = __nv_bfloat162(l0, l1);
            }
        }
    }
}

// ============================================================
// K2: axial attention via mma.sync bf16 3-pass split, 512 threads.
// (R14-exact: fp32 bufH/bufW epilogue)
// ============================================================
#define PS 136
#define QP 72

#define AT_TBUF 73728
#define AT_PH   139264
#define AT_PL   174080
#define AT_SMEM (3 * AT_TBUF)   // 221184

extern __shared__ char at_sm[];

__device__ __forceinline__ void attn_issue_qk(
    const __nv_bfloat16* s0, const __nv_bfloat16* s1,
    const __nv_bfloat16* s2, const __nv_bfloat16* s3,
    int s, uint32_t tb, int tid, int mode)
{
    const __nv_bfloat16* srcs[4] = { s0, s1, s2, s3 };
    const int d = s >> 1, off = (s & 1) * 64;
    if (mode == 0) {
        #pragma unroll
        for (int t = 0; t < 4; t++) {
            const __nv_bfloat16* src = srcs[t] + (size_t)d * HW + off;
            uint32_t dstb = tb + t * 18432;
            #pragma unroll
            for (int it = 0; it < 2; it++) {
                int idx = tid + it * NTA;
                int r = idx >> 3, c = idx & 7;
                cp16(dstb + r * 144 + c * 16, src + r * TOK + c * 8);
            }
        }
    } else {
        #pragma unroll
        for (int t = 0; t < 4; t++) {
            const __nv_bfloat16* src = srcs[t] + (size_t)d * HW + (size_t)off * TOK;
            uint32_t dstb = tb + t * 17408;
            #pragma unroll
            for (int it = 0; it < 2; it++) {
                int idx = tid + it * NTA;
                int r = idx >> 4, c = idx & 15;
                cp16(dstb + r * 272 + c * 16, src + r * TOK + c * 8);
            }
        }
    }
    cp_commit();
}

__device__ __forceinline__ void attn_issue_v(
    const __nv_bfloat16* vh, const __nv_bfloat16* vl, int d, uint32_t vb, int tid)
{
    #pragma unroll
    for (int sp = 0; sp < 2; sp++) {
        const __nv_bfloat16* src = (sp ? vl : vh) + (size_t)d * HW;
        uint32_t dstb = vb + sp * 34816;
        #pragma unroll
        for (int it = 0; it < 4; it++) {
            int idx = tid + it * NTA;
            int r = idx >> 4, c = idx & 15;
            cp16(dstb + r * 272 + c * 16, src + r * TOK + c * 8);
        }
    }
    cp_commit();
}

__global__ void __launch_bounds__(NTA) attn_mma_kernel()
{
    float* Ssm = reinterpret_cast<float*>(at_sm);
    __nv_bfloat16* Ph = reinterpret_cast<__nv_bfloat16*>(at_sm + AT_PH);
    __nv_bfloat16* Pl = reinterpret_cast<__nv_bfloat16*>(at_sm + AT_PL);

    const int tid = threadIdx.x;
    const int lane = tid & 31, warp = tid >> 5;
    const int wm = warp >> 2, wn = warp & 3;
    const int g = lane >> 2, tig = lane & 3;
    const int bh2 = blockIdx.x, mode = blockIdx.y;
    const int b = bh2 >> 3, head = bh2 & 7;
    const uint32_t sbase = smem_u32(at_sm);

    const size_t pbase = ((size_t)b * INNER + head * DH) * HW;
    const __nv_bfloat16* __restrict__ qh = g_q_hi + pbase;
    const __nv_bfloat16* __restrict__ ql = g_q_lo + pbase;
    const __nv_bfloat16* __restrict__ kh = g_k_hi + pbase;
    const __nv_bfloat16* __restrict__ kl = g_k_lo + pbase;
    const __nv_bfloat16* __restrict__ vh = g_v_hi + pbase;
    const __nv_bfloat16* __restrict__ vl = g_v_lo + pbase;

    // ================= phase 1: S = Q K^T =================
    {
        float acc[2][4][4];
        #pragma unroll
        for (int i = 0; i < 2; i++)
            #pragma unroll
            for (int j = 0; j < 4; j++)
                #pragma unroll
                for (int q = 0; q < 4; q++) acc[i][j][q] = 0.f;

        attn_issue_qk(qh, ql, kh, kl, 0, sbase,           tid, mode);
        attn_issue_qk(qh, ql, kh, kl, 1, sbase + AT_TBUF, tid, mode);

        for (int s = 0; s < 128; s++) {
            if (s < 127) { cp_wait<1>(); } else { cp_wait<0>(); }
            __syncthreads();

            const char* tbase = at_sm + (s % 3) * AT_TBUF;

            if (mode == 0) {
                const __nv_bfloat16* Qh = reinterpret_cast<const __nv_bfloat16*>(tbase);
                const __nv_bfloat16* Ql = reinterpret_cast<const __nv_bfloat16*>(tbase + 18432);
                const __nv_bfloat16* Kh = reinterpret_cast<const __nv_bfloat16*>(tbase + 36864);
                const __nv_bfloat16* Kl = reinterpret_cast<const __nv_bfloat16*>(tbase + 55296);
                #pragma unroll
                for (int ks = 0; ks < 4; ks++) {
                    const int kk = ks * 16;
                    uint32_t ah[2][4], al[2][4], bh[4][2], bl[4][2];
                    #pragma unroll
                    for (int mt = 0; mt < 2; mt++) {
                        uint32_t off = (wm*32 + mt*16 + (lane & 15)) * QP + kk + (lane >> 4) * 8;
                        ldsm4(smem_u32(Qh + off), ah[mt][0], ah[mt][1], ah[mt][2], ah[mt][3]);
                        ldsm4(smem_u32(Ql + off), al[mt][0], al[mt][1], al[mt][2], al[mt][3]);
                    }
                    #pragma unroll
                    for (int np = 0; np < 2; np++) {
                        int nrow = wn*32 + np*16 + (lane & 7) + ((lane >> 4) & 1) * 8;
                        int kcol = kk + ((lane >> 3) & 1) * 8;
                        uint32_t off = nrow * QP + kcol;
                        ldsm4(smem_u32(Kh + off), bh[np*2][0], bh[np*2][1], bh[np*2+1][0], bh[np*2+1][1]);
                        ldsm4(smem_u32(Kl + off), bl[np*2][0], bl[np*2][1], bl[np*2+1][0], bl[np*2+1][1]);
                    }
                    mma_triple2(acc, ah, al, bh, bl);
                }
            } else {
                const __nv_bfloat16* Qh = reinterpret_cast<const __nv_bfloat16*>(tbase);
                const __nv_bfloat16* Ql = reinterpret_cast<const __nv_bfloat16*>(tbase + 17408);
                const __nv_bfloat16* Kh = reinterpret_cast<const __nv_bfloat16*>(tbase + 34816);
                const __nv_bfloat16* Kl = reinterpret_cast<const __nv_bfloat16*>(tbase + 52224);
                #pragma unroll
                for (int ks = 0; ks < 4; ks++) {
                    const int kk = ks * 16;
                    uint32_t ah[2][4], al[2][4], bh[4][2], bl[4][2];
                    #pragma unroll
                    for (int mt = 0; mt < 2; mt++) {
                        uint32_t off = (kk + (lane & 7) + ((lane >> 4) & 1) * 8) * PS
                                       + wm*32 + mt*16 + ((lane >> 3) & 1) * 8;
                        ldsm4t(smem_u32(Qh + off), ah[mt][0], ah[mt][1], ah[mt][2], ah[mt][3]);
                        ldsm4t(smem_u32(Ql + off), al[mt][0], al[mt][1], al[mt][2], al[mt][3]);
                    }
                    #pragma unroll
                    for (int np = 0; np < 2; np++) {
                        int krow = kk + (lane & 7) + ((lane >> 3) & 1) * 8;
                        int ncol = wn*32 + np*16 + ((lane >> 4) & 1) * 8;
                        uint32_t off = krow * PS + ncol;
                        ldsm4t(smem_u32(Kh + off), bh[np*2][0], bh[np*2][1], bh[np*2+1][0], bh[np*2+1][1]);
                        ldsm4t(smem_u32(Kl + off), bl[np*2][0], bl[np*2][1], bl[np*2+1][0], bl[np*2+1][1]);
                    }
                    mma_triple2(acc, ah, al, bh, bl);
                }
            }

            if (s + 2 <= 127)
                attn_issue_qk(qh, ql, kh, kl, s + 2, sbase + ((s + 2) % 3) * AT_TBUF, tid, mode);
        }

        #pragma unroll
        for (int mt = 0; mt < 2; mt++) {
            int i0 = wm*32 + mt*16 + g;
            #pragma unroll
            for (int nt = 0; nt < 4; nt++) {
                int j0 = wn*32 + nt*8 + tig*2;
                Ssm[j0 * TOK + i0]           = acc[mt][nt][0];
                Ssm[(j0+1) * TOK + i0]       = acc[mt][nt][1];
                Ssm[j0 * TOK + i0 + 8]       = acc[mt][nt][2];
                Ssm[(j0+1) * TOK + i0 + 8]   = acc[mt][nt][3];
            }
        }
    }
    __syncthreads();

    // ================= softmax over j, write P hi/lo =================
    if (tid < TOK) {
        const int i = tid;
        float mx = -1e30f;
        for (int j = 0; j < TOK; j++) mx = fmaxf(mx, Ssm[j * TOK + i]);
        float s = 0.f;
        for (int j = 0; j < TOK; j++) {
            float e = __expf((Ssm[j * TOK + i] - mx) * 0.125f);
            s += e;
            Ssm[j * TOK + i] = e;
        }
        float inv = 1.f / s;
        for (int j = 0; j < TOK; j++) {
            float pv = Ssm[j * TOK + i] * inv;
            __nv_bfloat16 h, l;
            bf16_split(pv, h, l);
            Ph[j * PS + i] = h;
            Pl[j * PS + i] = l;
        }
    }
    __syncthreads();

    // ================= phase 2: O = P V =================
    float* outp = ((mode == 0) ? g_bufH : g_bufW) + pbase;

    attn_issue_v(vh, vl, 0, sbase, tid);

    for (int d = 0; d < DH; d++) {
        const int buf = d & 1;
        if (d < DH - 1) {
            attn_issue_v(vh, vl, d + 1, sbase + (buf ^ 1) * 69632, tid);
            cp_wait<1>();
        } else {
            cp_wait<0>();
        }
        __syncthreads();

        const __nv_bfloat16* Vh = reinterpret_cast<const __nv_bfloat16*>(at_sm + buf * 69632);
        const __nv_bfloat16* Vl = Vh + 128 * PS;

        float oacc[2][4][4];
        #pragma unroll
        for (int i = 0; i < 2; i++)
            #pragma unroll
            for (int j = 0; j < 4; j++)
                #pragma unroll
                for (int q = 0; q < 4; q++) oacc[i][j][q] = 0.f;

        if (mode == 0) {
            #pragma unroll
            for (int ks = 0; ks < 8; ks++) {
                const int kk = ks * 16;
                uint32_t ah[2][4], al[2][4], bh[4][2], bl[4][2];
                #pragma unroll
                for (int mt = 0; mt < 2; mt++) {
                    uint32_t off = (kk + (lane & 7) + ((lane >> 4) & 1) * 8) * PS
                                   + wm*32 + mt*16 + ((lane >> 3) & 1) * 8;
                    ldsm4t(smem_u32(Ph + off), ah[mt][0], ah[mt][1], ah[mt][2], ah[mt][3]);
                    ldsm4t(smem_u32(Pl + off), al[mt][0], al[mt][1], al[mt][2], al[mt][3]);
                }
                #pragma unroll
                for (int np = 0; np < 2; np++) {
                    int krow = kk + (lane & 7) + ((lane >> 3) & 1) * 8;
                    int ncol = wn*32 + np*16 + ((lane >> 4) & 1) * 8;
                    uint32_t off = krow * PS + ncol;
                    ldsm4t(smem_u32(Vh + off), bh[np*2][0], bh[np*2][1], bh[np*2+1][0], bh[np*2+1][1]);
                    ldsm4t(smem_u32(Vl + off), bl[np*2][0], bl[np*2][1], bl[np*2+1][0], bl[np*2+1][1]);
                }
                mma_triple2(oacc, ah, al, bh, bl);
            }
        } else {
            #pragma unroll
            for (int ks = 0; ks < 8; ks++) {
                const int kk = ks * 16;
                uint32_t ah[2][4], al[2][4], bh[4][2], bl[4][2];
                #pragma unroll
                for (int mt = 0; mt < 2; mt++) {
                    uint32_t off = (wm*32 + mt*16 + (lane & 15)) * PS + kk + (lane >> 4) * 8;
                    ldsm4(smem_u32(Vh + off), ah[mt][0], ah[mt][1], ah[mt][2], ah[mt][3]);
                    ldsm4(smem_u32(Vl + off), al[mt][0], al[mt][1], al[mt][2], al[mt][3]);
                }
                #pragma unroll
                for (int np = 0; np < 2; np++) {
                    int krow = kk + (lane & 7) + ((lane >> 3) & 1) * 8;
                    int ncol = wn*32 + np*16 + ((lane >> 4) & 1) * 8;
                    uint32_t off = krow * PS + ncol;
                    ldsm4t(smem_u32(Ph + off), bh[np*2][0], bh[np*2][1], bh[np*2+1][0], bh[np*2+1][1]);
                    ldsm4t(smem_u32(Pl + off), bl[np*2][0], bl[np*2][1], bl[np*2+1][0], bl[np*2+1][1]);
                }
                mma_triple2(oacc, ah, al, bh, bl);
            }
        }

        float* dstb = outp + (size_t)d * HW;
        #pragma unroll
        for (int mt = 0; mt < 2; mt++) {
            #pragma unroll
            for (int half = 0; half < 2; half++) {
                int m = wm*32 + mt*16 + g + half*8;
                float* rowp = dstb + (size_t)m * TOK;
                #pragma unroll
                for (int nt = 0; nt < 4; nt++) {
                    int col = wn*32 + nt*8 + tig*2;
                    *reinterpret_cast<float2*>(rowp + col) =
                        make_float2(oacc[mt][nt][half*2], oacc[mt][nt][half*2+1]);
                }
            }
        }
        __syncthreads();
    }
}

// ============================================================
// K2b: avg = 0.5*(bufH+bufW) -> bf16 hi/lo (elementwise)
// ============================================================
__global__ void __launch_bounds__(256) avg_split_kernel() {
    size_t i = ((size_t)blockIdx.x * 256 + threadIdx.x) * 4;
    float4 hv = *reinterpret_cast<const float4*>(g_bufH + i);
    float4 wv = *reinterpret_cast<const float4*>(g_bufW + i);
    float s0 = 0.5f * (hv.x + wv.x), s1 = 0.5f * (hv.y + wv.y);
    float s2 = 0.5f * (hv.z + wv.z), s3 = 0.5f * (hv.w + wv.w);
    __nv_bfloat16 h0, l0, h1, l1, h2, l2, h3, l3;
    bf16_split(s0, h0, l0); bf16_split(s1, h1, l1);
    bf16_split(s2, h2, l2); bf16_split(s3, h3, l3);
    *reinterpret_cast<__nv_bfloat162*>(g_av_hi + i)     = __nv_bfloat162(h0, h1);
    *reinterpret_cast<__nv_bfloat162*>(g_av_hi + i + 2) = __nv_bfloat162(h2, h3);
    *reinterpret_cast<__nv_bfloat162*>(g_av_lo + i)     = __nv_bfloat162(l0, l1);
    *reinterpret_cast<__nv_bfloat162*>(g_av_lo + i + 2) = __nv_bfloat162(l2, l3);
}

// ============================================================
// K3: out = wout @ av + b_out + x.  Pure GEMM, K=512, 8 slabs.
// CTA 128m x 256n, warp tile 64x64. B [k][hw]-major -> trans-B.
// stage: A_hi [128][72] @0, A_lo @18432, B_hi [64][264] @36864,
//        B_lo @70656. stage = 104448, 2 stages = 208896.
// ============================================================
#define K3P  72
#define K3BN 264
#define K3_STAGE 104448
#define K3_SMEM  (2 * K3_STAGE)   // 208896

extern __shared__ char k3_sm[];

__device__ __forceinline__ void k3_issue(int m0, int n0, int b, int k0, uint32_t tb, int tid) {
    {
        const __nv_bfloat16* srcs[2] = {
            g_wo_hi + (size_t)m0 * INNER + k0,
            g_wo_lo + (size_t)m0 * INNER + k0 };
        #pragma unroll
        for (int t = 0; t < 2; t++) {
            uint32_t dstb = tb + t * 18432;
            const __nv_bfloat16* src = srcs[t];
            #pragma unroll
            for (int it = 0; it < 4; it++) {
                int idx = tid + it * 256;
                int r = idx >> 3, c = idx & 7;
                cp16(dstb + r * 144 + c * 16, src + (size_t)r * INNER + c * 8);
            }
        }
    }
    {
        const __nv_bfloat16* srcs[2] = {
            g_av_hi + ((size_t)b * INNER + k0) * HW + n0,
            g_av_lo + ((size_t)b * INNER + k0) * HW + n0 };
        #pragma unroll
        for (int t = 0; t < 2; t++) {
            uint32_t dstb = tb + 36864 + t * 33792;
            const __nv_bfloat16* src = srcs[t];
            #pragma unroll
            for (int it = 0; it < 8; it++) {   // 64 rows x 32 chunks = 2048
                int idx = tid + it * 256;
                int r = idx >> 5, c = idx & 31;
                cp16(dstb + r * 528 + c * 16, src + (size_t)r * HW + c * 8);
            }
        }
    }
    cp_commit();
}

__global__ void __launch_bounds__(256) out_mma_kernel(
    const float* __restrict__ x, const float* __restrict__ bout, float* __restrict__ out)
{
    const int tid = threadIdx.x;
    const int lane = tid & 31, warp = tid >> 5;
    const int wm = warp >> 2, wn = warp & 3;
    const int m0 = blockIdx.x * 128;
    const int n0 = blockIdx.y * 256;
    const int b  = blockIdx.z;
    const uint32_t sbase = smem_u32(k3_sm);

    float acc[4][8][4];
    #pragma unroll
    for (int i = 0; i < 4; i++)
        #pragma unroll
        for (int j = 0; j < 8; j++)
            #pragma unroll
            for (int q = 0; q < 4; q++) acc[i][j][q] = 0.f;

    k3_issue(m0, n0, b, 0, sbase, tid);

    for (int s = 0; s < 8; s++) {
        if (s > 0) __syncthreads();
        if (s < 7)
            k3_issue(m0, n0, b, (s + 1) * 64, sbase + ((s + 1) & 1) * K3_STAGE, tid);
        if (s < 7) { cp_wait<1>(); } else { cp_wait<0>(); }
        __syncthreads();

        const char* tb = k3_sm + (s & 1) * K3_STAGE;
        const __nv_bfloat16* Ah = reinterpret_cast<const __nv_bfloat16*>(tb);
        const __nv_bfloat16* Al = reinterpret_cast<const __nv_bfloat16*>(tb + 18432);
        const __nv_bfloat16* Bh = reinterpret_cast<const __nv_bfloat16*>(tb + 36864);
        const __nv_bfloat16* Bl = reinterpret_cast<const __nv_bfloat16*>(tb + 70656);

        #pragma unroll
        for (int ks = 0; ks < 4; ks++) {
            const int kk = ks * 16;
            uint32_t ah[4][4], al[4][4];
            #pragma unroll
            for (int mt = 0; mt < 4; mt++) {
                uint32_t off = (wm * 64 + mt * 16 + (lane & 15)) * K3P + kk + (lane >> 4) * 8;
                ldsm4(smem_u32(Ah + off), ah[mt][0], ah[mt][1], ah[mt][2], ah[mt][3]);
                ldsm4(smem_u32(Al + off), al[mt][0], al[mt][1], al[mt][2], al[mt][3]);
            }
            #pragma unroll
            for (int nh = 0; nh < 2; nh++) {
                uint32_t bh[4][2], bl[4][2];
                #pragma unroll
                for (int np = 0; np < 2; np++) {
                    int krow = kk + (lane & 7) + ((lane >> 3) & 1) * 8;
                    int ncol = wn * 64 + nh * 32 + np * 16 + ((lane >> 4) & 1) * 8;
                    uint32_t off = krow * K3BN + ncol;
                    ldsm4t(smem_u32(Bh + off), bh[np*2][0], bh[np*2][1], bh[np*2+1][0], bh[np*2+1][1]);
                    ldsm4t(smem_u32(Bl + off), bl[np*2][0], bl[np*2][1], bl[np*2+1][0], bl[np*2+1][1]);
                }
                #pragma unroll
                for (int mt = 0; mt < 4; mt++)
                    #pragma unroll
                    for (int nt = 0; nt < 4; nt++) {
                        mma16816(acc[mt][nh*4+nt], ah[mt], bh[nt]);
                        mma16816(acc[mt][nh*4+nt], ah[mt], bl[nt]);
                        mma16816(acc[mt][nh*4+nt], al[mt], bh[nt]);
                    }
            }
        }
    }

    // epilogue: + bias + residual
    const int g = lane >> 2, tig = lane & 3;
    #pragma unroll
    for (int mt = 0; mt < 4; mt++) {
        int mbase = m0 + wm * 64 + mt * 16;
        #pragma unroll
        for (int half = 0; half < 2; half++) {
            int m = mbase + g + half * 8;
            float bias = bout[m];
            size_t rbase = ((size_t)b * CH + m) * HW + n0;
            #pragma unroll
            for (int nt = 0; nt < 8; nt++) {
                int col = wn * 64 + nt * 8 + tig * 2;
                float2 xv = *reinterpret_cast<const float2*>(x + rbase + col);
                *reinterpret_cast<float2*>(out + rbase + col) =
                    make_float2(acc[mt][nt][half*2]   + bias + xv.x,
                                acc[mt][nt][half*2+1] + bias + xv.y);
            }
        }
    }
}

// ============================================================
extern "C" void kernel_launch(void* const* d_in, const int* in_sizes, int n_in,
                              void* d_out, int out_size) {
    (void)in_sizes; (void)n_in; (void)out_size;
    const float* x    = (const float*)d_in[0];
    const float* wqkv = (const float*)d_in[1];
    const float* wout = (const float*)d_in[2];
    const float* bout = (const float*)d_in[3];
    float* out = (float*)d_out;

    cudaFuncSetAttribute(qkv_mma_kernel,  cudaFuncAttributeMaxDynamicSharedMemorySize, K1_SMEM);
    cudaFuncSetAttribute(attn_mma_kernel, cudaFuncAttributeMaxDynamicSharedMemorySize, AT_SMEM);
    cudaFuncSetAttribute(out_mma_kernel,  cudaFuncAttributeMaxDynamicSharedMemorySize, K3_SMEM);

    convert_w_kernel<<<(NWQKV + NWOUT) / 256, 256>>>(wqkv, wout);
    transpose_x_kernel<<<dim3(HW / 32, CH / 32, BATCH), 256>>>(x);
    qkv_mma_kernel<<<dim3(1536 / 128, HW / 256, BATCH), 256, K1_SMEM>>>();
    attn_mma_kernel<<<dim3(BATCH * HEADS, 2), NTA, AT_SMEM>>>();
    avg_split_kernel<<<(int)((size_t)BATCH * INNER * HW / 4 / 256), 256>>>();
    out_mma_kernel<<<dim3(CH / 128, HW / 256, BATCH), 256, K3_SMEM>>>(x, bout, out);
}